// round 2
// baseline (speedup 1.0000x reference)
#include <cuda_runtime.h>
#include <cuda_fp16.h>
#include <cstdint>

// Problem constants
#define NB   4096      // batch
#define HH   64        // hidden
#define NG   192       // 3*H gates
#define TPB  64        // 2 warps per CTA
#define RPW  16        // rows per warp (m16 MMA tile)
#define RPB  32        // rows per CTA
#define NCTA (NB / RPB) // 128 CTAs

// Weight-fragment SMEM: 3 matvecs x 24 n-tiles x 4 k-slabs x 32 lanes, uint2 each
#define WFRAG_ENTRIES (3 * 24 * 4 * 32)   // 9216 uint2 = 73728 B

// wfrag index: matvec m (0=w_hh0, 1=w_ih1, 2=w_hh1), n-tile nt (gate block of 8), k-slab s
#define WF(m, nt, s) wfrag[((((m) * 24 + (nt)) * 4 + (s)) * 32) + lane]

__device__ __forceinline__ void mma16816(float c[4], const uint32_t a[4], const uint2 b) {
    asm volatile(
        "mma.sync.aligned.m16n8k16.row.col.f32.f16.f16.f32 "
        "{%0,%1,%2,%3}, {%4,%5,%6,%7}, {%8,%9}, {%0,%1,%2,%3};\n"
        : "+f"(c[0]), "+f"(c[1]), "+f"(c[2]), "+f"(c[3])
        : "r"(a[0]), "r"(a[1]), "r"(a[2]), "r"(a[3]), "r"(b.x), "r"(b.y));
}

// accurate-enough fast sigmoid/tanh: MUFU.EX2 + MUFU.RCP, ~1e-6 rel err
__device__ __forceinline__ float sigm(float v) {
    return __fdividef(1.0f, 1.0f + __expf(-v));
}
__device__ __forceinline__ float tanh_fast(float v) {
    // 1 - 2/(e^{2v}+1); saturates correctly at +-1 (inf handled by division)
    return 1.0f - __fdividef(2.0f, __expf(2.0f * v) + 1.0f);
}
__device__ __forceinline__ uint32_t packh2(float a, float b) {
    half2 h = __floats2half2_rn(a, b);   // .x = a (low 16 bits), .y = b
    return *reinterpret_cast<uint32_t*>(&h);
}

__global__ void __launch_bounds__(TPB, 1)
gru_fused_kernel(const float* __restrict__ x,
                 const float* __restrict__ w_ih0, const float* __restrict__ w_hh0,
                 const float* __restrict__ b_ih0, const float* __restrict__ b_hh0,
                 const float* __restrict__ w_ih1, const float* __restrict__ w_hh1,
                 const float* __restrict__ b_ih1, const float* __restrict__ b_hh1,
                 const float* __restrict__ fc_w, const float* __restrict__ fc_b,
                 float* __restrict__ out, int T)
{
    extern __shared__ unsigned char smem[];
    uint2* wfrag = reinterpret_cast<uint2*>(smem);
    float* wih0s = reinterpret_cast<float*>(smem + WFRAG_ENTRIES * 8);
    float* bih0s = wih0s + NG;
    float* bhh0s = bih0s + NG;
    float* bih1s = bhh0s + NG;
    float* bhh1s = bih1s + NG;
    float* fcws  = bhh1s + NG;
    float* fcbs  = fcws + HH;

    const int tid = threadIdx.x;

    // ---- one-time weight prep: pack B-fragments (fp16) for the 3 matvecs ----
    // B fragment (m16n8k16, col-major B = W^T):
    //   b0,b1 = W[g][k0], W[g][k0+1];  b2,b3 = W[g][k0+8], W[g][k0+9]
    //   g = nt*8 + lane/4, k0 = s*16 + 2*(lane%4)
    for (int i = tid; i < WFRAG_ENTRIES; i += TPB) {
        int lane = i & 31;
        int s    = (i >> 5) & 3;
        int nt   = (i >> 7) % 24;
        int m    = (i >> 7) / 24;
        const float* W = (m == 0) ? w_hh0 : ((m == 1) ? w_ih1 : w_hh1);
        const float* row = W + (nt * 8 + (lane >> 2)) * HH;
        int k0 = s * 16 + 2 * (lane & 3);
        uint2 e;
        e.x = packh2(row[k0],     row[k0 + 1]);
        e.y = packh2(row[k0 + 8], row[k0 + 9]);
        wfrag[i] = e;
    }
    for (int i = tid; i < NG; i += TPB) {
        wih0s[i] = w_ih0[i];   // w_ih0 is [192,1]
        bih0s[i] = b_ih0[i];
        bhh0s[i] = b_hh0[i];
        bih1s[i] = b_ih1[i];
        bhh1s[i] = b_hh1[i];
    }
    for (int i = tid; i < HH; i += TPB) fcws[i] = fc_w[i];
    if (tid == 0) fcbs[0] = fc_b[0];
    __syncthreads();

    const int lane = tid & 31;
    const int warp = tid >> 5;
    const int rowbase = blockIdx.x * RPB + warp * RPW;
    const int q  = lane & 3;      // quad position -> column pair 2q, 2q+1
    const int r0 = lane >> 2;     // row-within-tile (and row+8)

    // State: fp32 carry in C-fragment layout, fp16 A-fragments for MMA input.
    // h1c/h2c index: 4*g + {0:(r0,j0) 1:(r0,j1) 2:(r0+8,j0) 3:(r0+8,j1)}, j0 = 8g+2q
    float    h1c[32], h2c[32];
    uint32_t hA1[16], hA2[16];
    #pragma unroll
    for (int i = 0; i < 32; i++) { h1c[i] = 0.0f; h2c[i] = 0.0f; }
    #pragma unroll
    for (int i = 0; i < 16; i++) { hA1[i] = 0u; hA2[i] = 0u; }

    const float2* bih0p = reinterpret_cast<const float2*>(bih0s);
    const float2* bhh0p = reinterpret_cast<const float2*>(bhh0s);
    const float2* bih1p = reinterpret_cast<const float2*>(bih1s);
    const float2* bhh1p = reinterpret_cast<const float2*>(bhh1s);
    const float2* wih0p = reinterpret_cast<const float2*>(wih0s);
    const float2* fcwp  = reinterpret_cast<const float2*>(fcws);

    const float* xrow = x + (size_t)rowbase * T;
    float xv = (lane < RPW) ? xrow[lane * T] : 0.0f;   // lane r holds x[row r, t]

    for (int t = 0; t < T; ++t) {
        float x0 = __shfl_sync(0xffffffffu, xv, r0);
        float x1 = __shfl_sync(0xffffffffu, xv, r0 + 8);
        float xnext = 0.0f;
        if (t + 1 < T && lane < RPW) xnext = xrow[lane * T + t + 1];

        // ================= layer 0 =================
        uint32_t hA1n[16];
        #pragma unroll
        for (int g = 0; g < 8; ++g) {
            // init accumulators with b_hh0 (r/z/n blocks at +0/+64/+128)
            float2 bR = bhh0p[      4 * g + q];
            float2 bZ = bhh0p[32 +  4 * g + q];
            float2 bN = bhh0p[64 +  4 * g + q];
            float cr[4] = {bR.x, bR.y, bR.x, bR.y};
            float cz[4] = {bZ.x, bZ.y, bZ.x, bZ.y};
            float cn[4] = {bN.x, bN.y, bN.x, bN.y};
            #pragma unroll
            for (int s = 0; s < 4; ++s) {
                mma16816(cr, &hA1[4 * s], WF(0, g,      s));
                mma16816(cz, &hA1[4 * s], WF(0, 8 + g,  s));
                mma16816(cn, &hA1[4 * s], WF(0, 16 + g, s));
            }
            // i-parts (exact fp32): x * w_ih0[g] + b_ih0[g]
            float2 wR = wih0p[     4 * g + q], pR = bih0p[     4 * g + q];
            float2 wZ = wih0p[32 + 4 * g + q], pZ = bih0p[32 + 4 * g + q];
            float2 wN = wih0p[64 + 4 * g + q], pN = bih0p[64 + 4 * g + q];
            float ir[4] = { fmaf(x0, wR.x, pR.x), fmaf(x0, wR.y, pR.y),
                            fmaf(x1, wR.x, pR.x), fmaf(x1, wR.y, pR.y) };
            float iz[4] = { fmaf(x0, wZ.x, pZ.x), fmaf(x0, wZ.y, pZ.y),
                            fmaf(x1, wZ.x, pZ.x), fmaf(x1, wZ.y, pZ.y) };
            float in_[4] = { fmaf(x0, wN.x, pN.x), fmaf(x0, wN.y, pN.y),
                             fmaf(x1, wN.x, pN.x), fmaf(x1, wN.y, pN.y) };
            float hn[4];
            #pragma unroll
            for (int i = 0; i < 4; ++i) {
                float rr = sigm(ir[i] + cr[i]);
                float zz = sigm(iz[i] + cz[i]);
                float nn = tanh_fast(fmaf(rr, cn[i], in_[i]));
                float hp = h1c[4 * g + i];
                float hv = fmaf(zz, hp - nn, nn);    // (1-z)*n + z*h
                h1c[4 * g + i] = hv;
                hn[i] = hv;
            }
            // C-frag -> A-frag: slab g/2, reg pair (g&1)*2
            int sl = g >> 1, off = (g & 1) * 2;
            hA1n[4 * sl + off]     = packh2(hn[0], hn[1]);
            hA1n[4 * sl + off + 1] = packh2(hn[2], hn[3]);
        }
        #pragma unroll
        for (int i = 0; i < 16; ++i) hA1[i] = hA1n[i];

        // ================= layer 1 =================
        uint32_t hA2n[16];
        #pragma unroll
        for (int g = 0; g < 8; ++g) {
            float2 biR = bih1p[     4 * g + q];
            float2 biZ = bih1p[32 + 4 * g + q];
            float2 biN = bih1p[64 + 4 * g + q];
            float2 bhR = bhh1p[     4 * g + q];
            float2 bhZ = bhh1p[32 + 4 * g + q];
            float2 bhN = bhh1p[64 + 4 * g + q];
            float air[4] = {biR.x, biR.y, biR.x, biR.y};
            float aiz[4] = {biZ.x, biZ.y, biZ.x, biZ.y};
            float ain[4] = {biN.x, biN.y, biN.x, biN.y};
            float dr[4]  = {bhR.x, bhR.y, bhR.x, bhR.y};
            float dz[4]  = {bhZ.x, bhZ.y, bhZ.x, bhZ.y};
            float dn[4]  = {bhN.x, bhN.y, bhN.x, bhN.y};
            #pragma unroll
            for (int s = 0; s < 4; ++s) {
                mma16816(air, &hA1[4 * s], WF(1, g,      s));  // gi1 = h1_new @ w_ih1^T
                mma16816(aiz, &hA1[4 * s], WF(1, 8 + g,  s));
                mma16816(ain, &hA1[4 * s], WF(1, 16 + g, s));
                mma16816(dr,  &hA2[4 * s], WF(2, g,      s));  // gh1 = h2_old @ w_hh1^T
                mma16816(dz,  &hA2[4 * s], WF(2, 8 + g,  s));
                mma16816(dn,  &hA2[4 * s], WF(2, 16 + g, s));
            }
            float hn[4];
            #pragma unroll
            for (int i = 0; i < 4; ++i) {
                float rr = sigm(air[i] + dr[i]);
                float zz = sigm(aiz[i] + dz[i]);
                float nn = tanh_fast(fmaf(rr, dn[i], ain[i]));
                float hp = h2c[4 * g + i];
                float hv = fmaf(zz, hp - nn, nn);
                h2c[4 * g + i] = hv;
                hn[i] = hv;
            }
            int sl = g >> 1, off = (g & 1) * 2;
            hA2n[4 * sl + off]     = packh2(hn[0], hn[1]);
            hA2n[4 * sl + off + 1] = packh2(hn[2], hn[3]);
        }
        #pragma unroll
        for (int i = 0; i < 16; ++i) hA2[i] = hA2n[i];

        xv = xnext;
    }

    // ---- final FC: out[b] = sum_j h2[b][j]*fc_w[j] + fc_b ----
    float p0 = 0.0f, p1 = 0.0f;
    #pragma unroll
    for (int g = 0; g < 8; ++g) {
        float2 fw = fcwp[4 * g + q];
        p0 += h2c[4 * g + 0] * fw.x + h2c[4 * g + 1] * fw.y;
        p1 += h2c[4 * g + 2] * fw.x + h2c[4 * g + 3] * fw.y;
    }
    p0 += __shfl_xor_sync(0xffffffffu, p0, 1);
    p0 += __shfl_xor_sync(0xffffffffu, p0, 2);
    p1 += __shfl_xor_sync(0xffffffffu, p1, 1);
    p1 += __shfl_xor_sync(0xffffffffu, p1, 2);
    if (q == 0) {
        float fb = fcbs[0];
        out[rowbase + r0]     = p0 + fb;
        out[rowbase + r0 + 8] = p1 + fb;
    }
}

extern "C" void kernel_launch(void* const* d_in, const int* in_sizes, int n_in,
                              void* d_out, int out_size) {
    const float* x     = (const float*)d_in[0];
    const float* w_ih0 = (const float*)d_in[1];
    const float* w_hh0 = (const float*)d_in[2];
    const float* b_ih0 = (const float*)d_in[3];
    const float* b_hh0 = (const float*)d_in[4];
    const float* w_ih1 = (const float*)d_in[5];
    const float* w_hh1 = (const float*)d_in[6];
    const float* b_ih1 = (const float*)d_in[7];
    const float* b_hh1 = (const float*)d_in[8];
    const float* fc_w  = (const float*)d_in[9];
    const float* fc_b  = (const float*)d_in[10];

    int T = in_sizes[0] / NB;   // 512

    size_t smem = (size_t)WFRAG_ENTRIES * 8 + 5 * NG * 4 + HH * 4 + 4;  // 77828 B
    cudaFuncSetAttribute(gru_fused_kernel,
                         cudaFuncAttributeMaxDynamicSharedMemorySize, (int)smem);

    gru_fused_kernel<<<NCTA, TPB, smem>>>(
        x, w_ih0, w_hh0, b_ih0, b_hh0,
        w_ih1, w_hh1, b_ih1, b_hh1,
        fc_w, fc_b, (float*)d_out, T);
}

// round 3
// speedup vs baseline: 3.5181x; 3.5181x over previous
#include <cuda_runtime.h>
#include <cuda_fp16.h>
#include <cstdint>

// Problem constants
#define NB   4096      // batch
#define HH   64        // hidden
#define NG   192       // 3*H gates
#define TPB  256       // 8 warps: 2 groups x 4 warps
#define RPG  16        // rows per group (m16 MMA tile)
#define RPB  32        // rows per CTA (2 groups)
#define NCTA (NB / RPB) // 128 CTAs

// Weight-fragment SMEM: 3 matvecs x 24 n-tiles x 4 k-slabs x 32 lanes, uint2 each
#define WFRAG_ENTRIES (3 * 24 * 4 * 32)   // 9216 uint2 = 73728 B
#define WFRAG_BYTES   (WFRAG_ENTRIES * 8)

// h-exchange buffer: 16 rows x 72 halves (pad 64->72 kills bank conflicts)
#define HPAD 72
#define HBUF_HALVES (RPG * HPAD)          // 1152 halves = 2304 B

// wfrag index: matvec m (0=w_hh0, 1=w_ih1, 2=w_hh1), n-tile nt (gate block of 8), k-slab s
#define WF(m, nt, s) wfrag[((((m) * 24 + (nt)) * 4 + (s)) * 32) + lane]

__device__ __forceinline__ void mma16816(float c[4], const uint32_t a[4], const uint2 b) {
    asm volatile(
        "mma.sync.aligned.m16n8k16.row.col.f32.f16.f16.f32 "
        "{%0,%1,%2,%3}, {%4,%5,%6,%7}, {%8,%9}, {%0,%1,%2,%3};\n"
        : "+f"(c[0]), "+f"(c[1]), "+f"(c[2]), "+f"(c[3])
        : "r"(a[0]), "r"(a[1]), "r"(a[2]), "r"(a[3]), "r"(b.x), "r"(b.y));
}

// single-MUFU nonlinearities (tanh.approx.f32, max abs err ~2^-11)
__device__ __forceinline__ float tanh_fast(float v) {
    float t;
    asm("tanh.approx.f32 %0, %1;" : "=f"(t) : "f"(v));
    return t;
}
__device__ __forceinline__ float sigm(float v) {
    return fmaf(0.5f, tanh_fast(0.5f * v), 0.5f);
}
__device__ __forceinline__ uint32_t packh2(float a, float b) {
    half2 h = __floats2half2_rn(a, b);   // .x = a (low 16 bits)
    return *reinterpret_cast<uint32_t*>(&h);
}

__global__ void __launch_bounds__(TPB, 1)
gru_fused_kernel(const float* __restrict__ x,
                 const float* __restrict__ w_ih0, const float* __restrict__ w_hh0,
                 const float* __restrict__ b_ih0, const float* __restrict__ b_hh0,
                 const float* __restrict__ w_ih1, const float* __restrict__ w_hh1,
                 const float* __restrict__ b_ih1, const float* __restrict__ b_hh1,
                 const float* __restrict__ fc_w, const float* __restrict__ fc_b,
                 float* __restrict__ out, int T)
{
    extern __shared__ unsigned char smem[];
    uint2* wfrag = reinterpret_cast<uint2*>(smem);
    __half* xs   = reinterpret_cast<__half*>(smem + WFRAG_BYTES);          // [T][32] fp16
    __half* hbuf = reinterpret_cast<__half*>(smem + WFRAG_BYTES + (size_t)RPB * T * 2);
    // hbuf: h1s[2 groups][HBUF_HALVES], then h2s[2][HBUF_HALVES]
    float* fbase = reinterpret_cast<float*>(reinterpret_cast<unsigned char*>(hbuf) + 4 * HBUF_HALVES * 2);
    float* wih0s = fbase;
    float* bih0s = wih0s + NG;
    float* bhh0s = bih0s + NG;
    float* bih1s = bhh0s + NG;
    float* bhh1s = bih1s + NG;
    float* fcws  = bhh1s + NG;
    float* fcbs  = fcws + HH;          // 1
    float* fcpart = fcbs + 1;          // [2 groups][4 warps][16 rows] = 128 floats

    const int tid = threadIdx.x;

    // ---- one-time weight prep: pack B-fragments (fp16) for the 3 matvecs ----
    for (int i = tid; i < WFRAG_ENTRIES; i += TPB) {
        int lane = i & 31;
        int s    = (i >> 5) & 3;
        int nt   = (i >> 7) % 24;
        int m    = (i >> 7) / 24;
        const float* W = (m == 0) ? w_hh0 : ((m == 1) ? w_ih1 : w_hh1);
        const float* row = W + (nt * 8 + (lane >> 2)) * HH;
        int k0 = s * 16 + 2 * (lane & 3);
        uint2 e;
        e.x = packh2(row[k0],     row[k0 + 1]);
        e.y = packh2(row[k0 + 8], row[k0 + 9]);
        wfrag[i] = e;
    }
    for (int i = tid; i < NG; i += TPB) {
        wih0s[i] = w_ih0[i];   // w_ih0 is [192,1]
        bih0s[i] = b_ih0[i];
        bhh0s[i] = b_hh0[i];
        bih1s[i] = b_ih1[i];
        bhh1s[i] = b_hh1[i];
    }
    for (int i = tid; i < HH; i += TPB) fcws[i] = fc_w[i];
    if (tid == 0) fcbs[0] = fc_b[0];

    // ---- stage x for this CTA's 32 rows into SMEM (fp16), coalesced reads ----
    {
        const int base = blockIdx.x * RPB;
        for (int i = tid; i < RPB * T; i += TPB) {
            int row = i / T;          // T consecutive tids hit consecutive t
            int t   = i - row * T;
            xs[t * RPB + row] = __float2half(x[(size_t)(base + row) * T + t]);
        }
    }
    __syncthreads();

    const int lane  = tid & 31;
    const int warp  = tid >> 5;
    const int group = warp >> 2;       // 0 or 1: which 16-row block
    const int wg    = warp & 3;        // warp-in-group: owns gate blocks {2wg, 2wg+1}
    const int rowbase = blockIdx.x * RPB + group * RPG;
    const int q  = lane & 3;           // quad -> column pair 2q, 2q+1
    const int r0 = lane >> 2;          // row-within-tile (and row+8)
    const int barid = group + 1;

    __half* h1sg = hbuf + group * HBUF_HALVES;
    __half* h2sg = hbuf + (2 + group) * HBUF_HALVES;
    const __half* xsg = xs + group * RPG;

    // per-warp fp32 carry for OWN 16 columns; full-width fp16 A-frags
    float    h1c[8], h2c[8];
    uint32_t hA1[16], hA2[16];
    #pragma unroll
    for (int i = 0; i < 8; i++) { h1c[i] = 0.0f; h2c[i] = 0.0f; }
    #pragma unroll
    for (int i = 0; i < 16; i++) { hA1[i] = 0u; hA2[i] = 0u; }

    const float2* bih0p = reinterpret_cast<const float2*>(bih0s);
    const float2* bhh0p = reinterpret_cast<const float2*>(bhh0s);
    const float2* bih1p = reinterpret_cast<const float2*>(bih1s);
    const float2* bhh1p = reinterpret_cast<const float2*>(bhh1s);
    const float2* wih0p = reinterpret_cast<const float2*>(wih0s);
    const float2* fcwp  = reinterpret_cast<const float2*>(fcws);

    for (int t = 0; t < T; ++t) {
        float x0 = __half2float(xsg[t * RPB + r0]);
        float x1 = __half2float(xsg[t * RPB + r0 + 8]);

        // ================= layer 0 : this warp's 2 gate-blocks =================
        #pragma unroll
        for (int gi = 0; gi < 2; ++gi) {
            const int g = 2 * wg + gi;
            float2 bR = bhh0p[      4 * g + q];
            float2 bZ = bhh0p[32 +  4 * g + q];
            float2 bN = bhh0p[64 +  4 * g + q];
            float cr[4] = {bR.x, bR.y, bR.x, bR.y};
            float cz[4] = {bZ.x, bZ.y, bZ.x, bZ.y};
            float cn[4] = {bN.x, bN.y, bN.x, bN.y};
            #pragma unroll
            for (int s = 0; s < 4; ++s) {
                mma16816(cr, &hA1[4 * s], WF(0, g,      s));
                mma16816(cz, &hA1[4 * s], WF(0, 8 + g,  s));
                mma16816(cn, &hA1[4 * s], WF(0, 16 + g, s));
            }
            float2 wR = wih0p[     4 * g + q], pR = bih0p[     4 * g + q];
            float2 wZ = wih0p[32 + 4 * g + q], pZ = bih0p[32 + 4 * g + q];
            float2 wN = wih0p[64 + 4 * g + q], pN = bih0p[64 + 4 * g + q];
            float ir[4] = { fmaf(x0, wR.x, pR.x), fmaf(x0, wR.y, pR.y),
                            fmaf(x1, wR.x, pR.x), fmaf(x1, wR.y, pR.y) };
            float iz[4] = { fmaf(x0, wZ.x, pZ.x), fmaf(x0, wZ.y, pZ.y),
                            fmaf(x1, wZ.x, pZ.x), fmaf(x1, wZ.y, pZ.y) };
            float in_[4] = { fmaf(x0, wN.x, pN.x), fmaf(x0, wN.y, pN.y),
                             fmaf(x1, wN.x, pN.x), fmaf(x1, wN.y, pN.y) };
            float hn[4];
            #pragma unroll
            for (int i = 0; i < 4; ++i) {
                float rr = sigm(ir[i] + cr[i]);
                float zz = sigm(iz[i] + cz[i]);
                float nn = tanh_fast(fmaf(rr, cn[i], in_[i]));
                float hp = h1c[4 * gi + i];
                float hv = fmaf(zz, hp - nn, nn);
                h1c[4 * gi + i] = hv;
                hn[i] = hv;
            }
            const int j0 = 8 * g + 2 * q;
            *reinterpret_cast<uint32_t*>(&h1sg[r0 * HPAD + j0])       = packh2(hn[0], hn[1]);
            *reinterpret_cast<uint32_t*>(&h1sg[(r0 + 8) * HPAD + j0]) = packh2(hn[2], hn[3]);
        }
        asm volatile("bar.sync %0, %1;" :: "r"(barid), "n"(128) : "memory");
        // gather full h1 A-fragments
        #pragma unroll
        for (int s = 0; s < 4; ++s) {
            hA1[4 * s + 0] = *reinterpret_cast<const uint32_t*>(&h1sg[r0 * HPAD + 16 * s + 2 * q]);
            hA1[4 * s + 1] = *reinterpret_cast<const uint32_t*>(&h1sg[(r0 + 8) * HPAD + 16 * s + 2 * q]);
            hA1[4 * s + 2] = *reinterpret_cast<const uint32_t*>(&h1sg[r0 * HPAD + 16 * s + 8 + 2 * q]);
            hA1[4 * s + 3] = *reinterpret_cast<const uint32_t*>(&h1sg[(r0 + 8) * HPAD + 16 * s + 8 + 2 * q]);
        }

        // ================= layer 1 : this warp's 2 gate-blocks =================
        #pragma unroll
        for (int gi = 0; gi < 2; ++gi) {
            const int g = 2 * wg + gi;
            float2 biR = bih1p[     4 * g + q];
            float2 biZ = bih1p[32 + 4 * g + q];
            float2 biN = bih1p[64 + 4 * g + q];
            float2 bhR = bhh1p[     4 * g + q];
            float2 bhZ = bhh1p[32 + 4 * g + q];
            float2 bhN = bhh1p[64 + 4 * g + q];
            float air[4] = {biR.x, biR.y, biR.x, biR.y};
            float aiz[4] = {biZ.x, biZ.y, biZ.x, biZ.y};
            float ain[4] = {biN.x, biN.y, biN.x, biN.y};
            float dr[4]  = {bhR.x, bhR.y, bhR.x, bhR.y};
            float dz[4]  = {bhZ.x, bhZ.y, bhZ.x, bhZ.y};
            float dn[4]  = {bhN.x, bhN.y, bhN.x, bhN.y};
            #pragma unroll
            for (int s = 0; s < 4; ++s) {
                mma16816(air, &hA1[4 * s], WF(1, g,      s));
                mma16816(aiz, &hA1[4 * s], WF(1, 8 + g,  s));
                mma16816(ain, &hA1[4 * s], WF(1, 16 + g, s));
                mma16816(dr,  &hA2[4 * s], WF(2, g,      s));
                mma16816(dz,  &hA2[4 * s], WF(2, 8 + g,  s));
                mma16816(dn,  &hA2[4 * s], WF(2, 16 + g, s));
            }
            float hn[4];
            #pragma unroll
            for (int i = 0; i < 4; ++i) {
                float rr = sigm(air[i] + dr[i]);
                float zz = sigm(aiz[i] + dz[i]);
                float nn = tanh_fast(fmaf(rr, dn[i], ain[i]));
                float hp = h2c[4 * gi + i];
                float hv = fmaf(zz, hp - nn, nn);
                h2c[4 * gi + i] = hv;
                hn[i] = hv;
            }
            const int j0 = 8 * g + 2 * q;
            *reinterpret_cast<uint32_t*>(&h2sg[r0 * HPAD + j0])       = packh2(hn[0], hn[1]);
            *reinterpret_cast<uint32_t*>(&h2sg[(r0 + 8) * HPAD + j0]) = packh2(hn[2], hn[3]);
        }
        asm volatile("bar.sync %0, %1;" :: "r"(barid), "n"(128) : "memory");
        #pragma unroll
        for (int s = 0; s < 4; ++s) {
            hA2[4 * s + 0] = *reinterpret_cast<const uint32_t*>(&h2sg[r0 * HPAD + 16 * s + 2 * q]);
            hA2[4 * s + 1] = *reinterpret_cast<const uint32_t*>(&h2sg[(r0 + 8) * HPAD + 16 * s + 2 * q]);
            hA2[4 * s + 2] = *reinterpret_cast<const uint32_t*>(&h2sg[r0 * HPAD + 16 * s + 8 + 2 * q]);
            hA2[4 * s + 3] = *reinterpret_cast<const uint32_t*>(&h2sg[(r0 + 8) * HPAD + 16 * s + 8 + 2 * q]);
        }
    }

    // ---- final FC: partial dot over this warp's 16 columns, then cross-warp sum ----
    float p0 = 0.0f, p1 = 0.0f;
    #pragma unroll
    for (int gi = 0; gi < 2; ++gi) {
        const int g = 2 * wg + gi;
        float2 fw = fcwp[4 * g + q];
        p0 += h2c[4 * gi + 0] * fw.x + h2c[4 * gi + 1] * fw.y;
        p1 += h2c[4 * gi + 2] * fw.x + h2c[4 * gi + 3] * fw.y;
    }
    p0 += __shfl_xor_sync(0xffffffffu, p0, 1);
    p0 += __shfl_xor_sync(0xffffffffu, p0, 2);
    p1 += __shfl_xor_sync(0xffffffffu, p1, 1);
    p1 += __shfl_xor_sync(0xffffffffu, p1, 2);
    if (q == 0) {
        fcpart[(group * 4 + wg) * RPG + r0]     = p0;
        fcpart[(group * 4 + wg) * RPG + r0 + 8] = p1;
    }
    asm volatile("bar.sync %0, %1;" :: "r"(barid), "n"(128) : "memory");
    if (wg == 0 && lane < RPG) {
        float s = fcbs[0];
        #pragma unroll
        for (int w = 0; w < 4; ++w)
            s += fcpart[(group * 4 + w) * RPG + lane];
        out[rowbase + lane] = s;
    }
}

extern "C" void kernel_launch(void* const* d_in, const int* in_sizes, int n_in,
                              void* d_out, int out_size) {
    const float* x     = (const float*)d_in[0];
    const float* w_ih0 = (const float*)d_in[1];
    const float* w_hh0 = (const float*)d_in[2];
    const float* b_ih0 = (const float*)d_in[3];
    const float* b_hh0 = (const float*)d_in[4];
    const float* w_ih1 = (const float*)d_in[5];
    const float* w_hh1 = (const float*)d_in[6];
    const float* b_ih1 = (const float*)d_in[7];
    const float* b_hh1 = (const float*)d_in[8];
    const float* fc_w  = (const float*)d_in[9];
    const float* fc_b  = (const float*)d_in[10];

    int T = in_sizes[0] / NB;   // 512

    size_t smem = (size_t)WFRAG_BYTES          // 73728: weight fragments
                + (size_t)RPB * T * 2          // 32768: x staged fp16
                + 4 * HBUF_HALVES * 2          //  9216: h1/h2 exchange (2 groups)
                + (5 * NG + HH + 1 + 128) * 4; //  4612: biases + fc + partials
    cudaFuncSetAttribute(gru_fused_kernel,
                         cudaFuncAttributeMaxDynamicSharedMemorySize, (int)smem);

    gru_fused_kernel<<<NCTA, TPB, smem>>>(
        x, w_ih0, w_hh0, b_ih0, b_hh0,
        w_ih1, w_hh1, b_ih1, b_hh1,
        fc_w, fc_b, (float*)d_out, T);
}

// round 4
// speedup vs baseline: 5.1484x; 1.4634x over previous
#include <cuda_runtime.h>
#include <cuda_fp16.h>
#include <cstdint>

// Problem constants
#define NB   4096      // batch
#define HH   64        // hidden
#define NG   192       // 3*H gates
#define TPB  256       // 8 warps: 2 groups x 4 warps
#define RPG  16        // rows per group (m16 MMA tile)
#define RPB  32        // rows per CTA (2 groups)
#define NCTA (NB / RPB) // 128 CTAs

// Weight-fragment staging SMEM (init only): 3 matvecs x 24 n-tiles x 4 k-slabs x 32 lanes
#define WFRAG_ENTRIES (3 * 24 * 4 * 32)   // 9216 uint2 = 73728 B
#define WFRAG_BYTES   (WFRAG_ENTRIES * 8)

// h-exchange buffer: 16 rows x 72 halves (pad 64->72 kills bank conflicts)
#define HPAD 72
#define HBUF_HALVES (RPG * HPAD)          // 1152 halves = 2304 B

#define WF(m, nt, s) wfrag[((((m) * 24 + (nt)) * 4 + (s)) * 32) + lane]

__device__ __forceinline__ void mma16816(float c[4], const uint32_t a[4], const uint2 b) {
    asm volatile(
        "mma.sync.aligned.m16n8k16.row.col.f32.f16.f16.f32 "
        "{%0,%1,%2,%3}, {%4,%5,%6,%7}, {%8,%9}, {%0,%1,%2,%3};\n"
        : "+f"(c[0]), "+f"(c[1]), "+f"(c[2]), "+f"(c[3])
        : "r"(a[0]), "r"(a[1]), "r"(a[2]), "r"(a[3]), "r"(b.x), "r"(b.y));
}

// single-MUFU nonlinearities (tanh.approx.f32)
__device__ __forceinline__ float tanh_fast(float v) {
    float t;
    asm("tanh.approx.f32 %0, %1;" : "=f"(t) : "f"(v));
    return t;
}
__device__ __forceinline__ float sigm(float v) {
    return fmaf(0.5f, tanh_fast(0.5f * v), 0.5f);
}
__device__ __forceinline__ uint32_t packh2(float a, float b) {
    half2 h = __floats2half2_rn(a, b);
    return *reinterpret_cast<uint32_t*>(&h);
}

__global__ void __launch_bounds__(TPB, 1)
gru_fused_kernel(const float* __restrict__ x,
                 const float* __restrict__ w_ih0, const float* __restrict__ w_hh0,
                 const float* __restrict__ b_ih0, const float* __restrict__ b_hh0,
                 const float* __restrict__ w_ih1, const float* __restrict__ w_hh1,
                 const float* __restrict__ b_ih1, const float* __restrict__ b_hh1,
                 const float* __restrict__ fc_w, const float* __restrict__ fc_b,
                 float* __restrict__ out, int T)
{
    extern __shared__ unsigned char smem[];
    uint2* wfrag = reinterpret_cast<uint2*>(smem);
    __half* xs   = reinterpret_cast<__half*>(smem + WFRAG_BYTES);          // [T][32] fp16
    __half* hbuf = reinterpret_cast<__half*>(smem + WFRAG_BYTES + (size_t)RPB * T * 2);
    float* fbase = reinterpret_cast<float*>(reinterpret_cast<unsigned char*>(hbuf) + 4 * HBUF_HALVES * 2);
    float* brz0s  = fbase;             // 128: bih0+bhh0 for r,z sections
    float* bihN0s = brz0s + 128;       // 64
    float* bhhN0s = bihN0s + 64;       // 64
    float* wih0s  = bhhN0s + 64;       // 192
    float* brz1s  = wih0s + NG;        // 128
    float* bihN1s = brz1s + 128;       // 64
    float* bhhN1s = bihN1s + 64;       // 64
    float* fcws   = bhhN1s + 64;       // 64
    float* fcbs   = fcws + HH;         // 1
    float* fcpart = fcbs + 1;          // 128

    const int tid = threadIdx.x;

    // ---- one-time weight prep: pack B-fragments (fp16) into staging SMEM ----
    for (int i = tid; i < WFRAG_ENTRIES; i += TPB) {
        int lane = i & 31;
        int s    = (i >> 5) & 3;
        int nt   = (i >> 7) % 24;
        int m    = (i >> 7) / 24;
        const float* W = (m == 0) ? w_hh0 : ((m == 1) ? w_ih1 : w_hh1);
        const float* row = W + (nt * 8 + (lane >> 2)) * HH;
        int k0 = s * 16 + 2 * (lane & 3);
        uint2 e;
        e.x = packh2(row[k0],     row[k0 + 1]);
        e.y = packh2(row[k0 + 8], row[k0 + 9]);
        wfrag[i] = e;
    }
    for (int i = tid; i < 128; i += TPB) {
        brz0s[i] = b_ih0[i] + b_hh0[i];
        brz1s[i] = b_ih1[i] + b_hh1[i];
    }
    for (int i = tid; i < 64; i += TPB) {
        bihN0s[i] = b_ih0[128 + i];
        bhhN0s[i] = b_hh0[128 + i];
        bihN1s[i] = b_ih1[128 + i];
        bhhN1s[i] = b_hh1[128 + i];
        fcws[i]   = fc_w[i];
    }
    for (int i = tid; i < NG; i += TPB) wih0s[i] = w_ih0[i];
    if (tid == 0) fcbs[0] = fc_b[0];

    // ---- stage x for this CTA's 32 rows into SMEM (fp16), coalesced reads ----
    {
        const int base = blockIdx.x * RPB;
        for (int i = tid; i < RPB * T; i += TPB) {
            int row = i / T;
            int t   = i - row * T;
            xs[t * RPB + row] = __float2half(x[(size_t)(base + row) * T + t]);
        }
    }
    __syncthreads();

    const int lane  = tid & 31;
    const int warp  = tid >> 5;
    const int group = warp >> 2;
    const int wg    = warp & 3;        // owns gate-blocks {2wg, 2wg+1}
    const int rowbase = blockIdx.x * RPB + group * RPG;
    const int q  = lane & 3;
    const int r0 = lane >> 2;
    const int barid = group + 1;

    __half* h1sg = hbuf + group * HBUF_HALVES;
    __half* h2sg = hbuf + (2 + group) * HBUF_HALVES;
    const __half* xsg = xs + group * RPG;

    // ---- hoist this warp's B-fragments into registers: [gi][kind r/z/n][s] ----
    uint2 wfh0[2][3][4], wfi1[2][3][4], wfh1[2][3][4];
    #pragma unroll
    for (int gi = 0; gi < 2; ++gi) {
        const int g = 2 * wg + gi;
        #pragma unroll
        for (int k = 0; k < 3; ++k) {
            const int nt = 8 * k + g;
            #pragma unroll
            for (int s = 0; s < 4; ++s) {
                wfh0[gi][k][s] = WF(0, nt, s);
                wfi1[gi][k][s] = WF(1, nt, s);
                wfh1[gi][k][s] = WF(2, nt, s);
            }
        }
    }

    float    h1c[8], h2c[8];
    uint32_t hA1[16], hA2[16];
    #pragma unroll
    for (int i = 0; i < 8; i++) { h1c[i] = 0.0f; h2c[i] = 0.0f; }
    #pragma unroll
    for (int i = 0; i < 16; i++) { hA1[i] = 0u; hA2[i] = 0u; }

    const float2* brz0p  = reinterpret_cast<const float2*>(brz0s);
    const float2* bihN0p = reinterpret_cast<const float2*>(bihN0s);
    const float2* bhhN0p = reinterpret_cast<const float2*>(bhhN0s);
    const float2* wih0p  = reinterpret_cast<const float2*>(wih0s);
    const float2* brz1p  = reinterpret_cast<const float2*>(brz1s);
    const float2* bihN1p = reinterpret_cast<const float2*>(bihN1s);
    const float2* bhhN1p = reinterpret_cast<const float2*>(bhhN1s);
    const float2* fcwp   = reinterpret_cast<const float2*>(fcws);

    for (int t = 0; t < T; ++t) {
        float x0 = __half2float(xsg[t * RPB + r0]);
        float x1 = __half2float(xsg[t * RPB + r0 + 8]);

        // ================= layer 0 =================
        #pragma unroll
        for (int gi = 0; gi < 2; ++gi) {
            const int g = 2 * wg + gi;
            float2 bR = brz0p[      4 * g + q];   // combined bih+bhh (r)
            float2 bZ = brz0p[32 +  4 * g + q];   // combined (z)
            float2 bN = bhhN0p[4 * g + q];        // bhh (n)
            float cr[4] = {bR.x, bR.y, bR.x, bR.y};
            float cz[4] = {bZ.x, bZ.y, bZ.x, bZ.y};
            float cn[4] = {bN.x, bN.y, bN.x, bN.y};
            #pragma unroll
            for (int s = 0; s < 4; ++s) {
                mma16816(cr, &hA1[4 * s], wfh0[gi][0][s]);
                mma16816(cz, &hA1[4 * s], wfh0[gi][1][s]);
                mma16816(cn, &hA1[4 * s], wfh0[gi][2][s]);
            }
            float2 wR = wih0p[     4 * g + q];
            float2 wZ = wih0p[32 + 4 * g + q];
            float2 wN = wih0p[64 + 4 * g + q];
            float2 pN = bihN0p[4 * g + q];
            float xr[4] = {x0, x0, x1, x1};
            float wRr[4] = {wR.x, wR.y, wR.x, wR.y};
            float wZr[4] = {wZ.x, wZ.y, wZ.x, wZ.y};
            float wNr[4] = {wN.x, wN.y, wN.x, wN.y};
            float pNr[4] = {pN.x, pN.y, pN.x, pN.y};
            float hn[4];
            #pragma unroll
            for (int i = 0; i < 4; ++i) {
                float rr = sigm(fmaf(xr[i], wRr[i], cr[i]));
                float zz = sigm(fmaf(xr[i], wZr[i], cz[i]));
                float in_ = fmaf(xr[i], wNr[i], pNr[i]);
                float nn = tanh_fast(fmaf(rr, cn[i], in_));
                float hp = h1c[4 * gi + i];
                float hv = fmaf(zz, hp - nn, nn);
                h1c[4 * gi + i] = hv;
                hn[i] = hv;
            }
            const int j0 = 8 * g + 2 * q;
            *reinterpret_cast<uint32_t*>(&h1sg[r0 * HPAD + j0])       = packh2(hn[0], hn[1]);
            *reinterpret_cast<uint32_t*>(&h1sg[(r0 + 8) * HPAD + j0]) = packh2(hn[2], hn[3]);
        }
        asm volatile("bar.sync %0, %1;" :: "r"(barid), "n"(128) : "memory");
        #pragma unroll
        for (int s = 0; s < 4; ++s) {
            hA1[4 * s + 0] = *reinterpret_cast<const uint32_t*>(&h1sg[r0 * HPAD + 16 * s + 2 * q]);
            hA1[4 * s + 1] = *reinterpret_cast<const uint32_t*>(&h1sg[(r0 + 8) * HPAD + 16 * s + 2 * q]);
            hA1[4 * s + 2] = *reinterpret_cast<const uint32_t*>(&h1sg[r0 * HPAD + 16 * s + 8 + 2 * q]);
            hA1[4 * s + 3] = *reinterpret_cast<const uint32_t*>(&h1sg[(r0 + 8) * HPAD + 16 * s + 8 + 2 * q]);
        }

        // ================= layer 1 =================
        #pragma unroll
        for (int gi = 0; gi < 2; ++gi) {
            const int g = 2 * wg + gi;
            float2 bR = brz1p[      4 * g + q];   // combined bih+bhh (r)
            float2 bZ = brz1p[32 +  4 * g + q];
            float2 biN = bihN1p[4 * g + q];
            float2 bhN = bhhN1p[4 * g + q];
            float air[4] = {bR.x, bR.y, bR.x, bR.y};
            float aiz[4] = {bZ.x, bZ.y, bZ.x, bZ.y};
            float ain[4] = {biN.x, biN.y, biN.x, biN.y};
            float dr[4]  = {0.f, 0.f, 0.f, 0.f};
            float dz[4]  = {0.f, 0.f, 0.f, 0.f};
            float dn[4]  = {bhN.x, bhN.y, bhN.x, bhN.y};
            #pragma unroll
            for (int s = 0; s < 4; ++s) {
                mma16816(air, &hA1[4 * s], wfi1[gi][0][s]);
                mma16816(aiz, &hA1[4 * s], wfi1[gi][1][s]);
                mma16816(ain, &hA1[4 * s], wfi1[gi][2][s]);
                mma16816(dr,  &hA2[4 * s], wfh1[gi][0][s]);
                mma16816(dz,  &hA2[4 * s], wfh1[gi][1][s]);
                mma16816(dn,  &hA2[4 * s], wfh1[gi][2][s]);
            }
            float hn[4];
            #pragma unroll
            for (int i = 0; i < 4; ++i) {
                float rr = sigm(air[i] + dr[i]);
                float zz = sigm(aiz[i] + dz[i]);
                float nn = tanh_fast(fmaf(rr, dn[i], ain[i]));
                float hp = h2c[4 * gi + i];
                float hv = fmaf(zz, hp - nn, nn);
                h2c[4 * gi + i] = hv;
                hn[i] = hv;
            }
            const int j0 = 8 * g + 2 * q;
            *reinterpret_cast<uint32_t*>(&h2sg[r0 * HPAD + j0])       = packh2(hn[0], hn[1]);
            *reinterpret_cast<uint32_t*>(&h2sg[(r0 + 8) * HPAD + j0]) = packh2(hn[2], hn[3]);
        }
        asm volatile("bar.sync %0, %1;" :: "r"(barid), "n"(128) : "memory");
        #pragma unroll
        for (int s = 0; s < 4; ++s) {
            hA2[4 * s + 0] = *reinterpret_cast<const uint32_t*>(&h2sg[r0 * HPAD + 16 * s + 2 * q]);
            hA2[4 * s + 1] = *reinterpret_cast<const uint32_t*>(&h2sg[(r0 + 8) * HPAD + 16 * s + 2 * q]);
            hA2[4 * s + 2] = *reinterpret_cast<const uint32_t*>(&h2sg[r0 * HPAD + 16 * s + 8 + 2 * q]);
            hA2[4 * s + 3] = *reinterpret_cast<const uint32_t*>(&h2sg[(r0 + 8) * HPAD + 16 * s + 8 + 2 * q]);
        }
    }

    // ---- final FC ----
    float p0 = 0.0f, p1 = 0.0f;
    #pragma unroll
    for (int gi = 0; gi < 2; ++gi) {
        const int g = 2 * wg + gi;
        float2 fw = fcwp[4 * g + q];
        p0 += h2c[4 * gi + 0] * fw.x + h2c[4 * gi + 1] * fw.y;
        p1 += h2c[4 * gi + 2] * fw.x + h2c[4 * gi + 3] * fw.y;
    }
    p0 += __shfl_xor_sync(0xffffffffu, p0, 1);
    p0 += __shfl_xor_sync(0xffffffffu, p0, 2);
    p1 += __shfl_xor_sync(0xffffffffu, p1, 1);
    p1 += __shfl_xor_sync(0xffffffffu, p1, 2);
    if (q == 0) {
        fcpart[(group * 4 + wg) * RPG + r0]     = p0;
        fcpart[(group * 4 + wg) * RPG + r0 + 8] = p1;
    }
    asm volatile("bar.sync %0, %1;" :: "r"(barid), "n"(128) : "memory");
    if (wg == 0 && lane < RPG) {
        float s = fcbs[0];
        #pragma unroll
        for (int w = 0; w < 4; ++w)
            s += fcpart[(group * 4 + w) * RPG + lane];
        out[rowbase + lane] = s;
    }
}

extern "C" void kernel_launch(void* const* d_in, const int* in_sizes, int n_in,
                              void* d_out, int out_size) {
    const float* x     = (const float*)d_in[0];
    const float* w_ih0 = (const float*)d_in[1];
    const float* w_hh0 = (const float*)d_in[2];
    const float* b_ih0 = (const float*)d_in[3];
    const float* b_hh0 = (const float*)d_in[4];
    const float* w_ih1 = (const float*)d_in[5];
    const float* w_hh1 = (const float*)d_in[6];
    const float* b_ih1 = (const float*)d_in[7];
    const float* b_hh1 = (const float*)d_in[8];
    const float* fc_w  = (const float*)d_in[9];
    const float* fc_b  = (const float*)d_in[10];

    int T = in_sizes[0] / NB;   // 512

    size_t smem = (size_t)WFRAG_BYTES          // 73728: weight-frag staging (init only)
                + (size_t)RPB * T * 2          // 32768: x staged fp16
                + 4 * HBUF_HALVES * 2          //  9216: h1/h2 exchange
                + (128 + 64 + 64 + NG + 128 + 64 + 64 + 64 + 1 + 128) * 4;
    cudaFuncSetAttribute(gru_fused_kernel,
                         cudaFuncAttributeMaxDynamicSharedMemorySize, (int)smem);

    gru_fused_kernel<<<NCTA, TPB, smem>>>(
        x, w_ih0, w_hh0, b_ih0, b_hh0,
        w_ih1, w_hh1, b_ih1, b_hh1,
        fc_w, fc_b, (float*)d_out, T);
}